// round 14
// baseline (speedup 1.0000x reference)
#include <cuda_runtime.h>

// softmax(f[n]+g[m]) over m cancels f[n] -> all output rows identical.
// Single fused kernel, 64 CTAs x 544 thr (17 warps):
//   stage A: 128 thr compute e*x row products -> smem transpose ->
//            17 warps col-reduce (85 SHFL/CTA instead of 340) -> 17-float partial
//   barrier: TICKET barrier (monotonic, no reset, replay-safe; 2^32 % 64 == 0)
//   stage B: 17 warps reduce global partials, 128 thr compute row, 512 thr store 4MB.

#define NB 64
#define NT 544          // 17 warps: one per reduced column
#define D_IN 16
#define DH   18
#define SA_STRIDE 19    // odd stride: conflict-free smem transpose

__device__ float g_part[17 * NB];            // [col][block]
__device__ unsigned int g_arrive = 0;        // monotonic ticket counter

__device__ __forceinline__ unsigned int atom_add_release_gpu(unsigned int* p) {
    unsigned int old;
    asm volatile("atom.add.release.gpu.global.u32 %0, [%1], 1;"
                 : "=r"(old) : "l"(p) : "memory");
    return old;
}
__device__ __forceinline__ unsigned int ld_acquire_gpu(const unsigned int* p) {
    unsigned int v;
    asm volatile("ld.acquire.gpu.global.u32 %0, [%1];" : "=r"(v) : "l"(p) : "memory");
    return v;
}

__global__ void __launch_bounds__(NT, 1) fused_kernel(
    const float* __restrict__ x,
    const float* __restrict__ W,
    const float* __restrict__ a,
    const float* __restrict__ Wk,
    float* __restrict__ out)
{
    __shared__ float wa2[16];
    __shared__ float sA[128 * SA_STRIDE];   // row r: products at sA[r*19 + k]
    __shared__ float red[17];
    __shared__ float orow[128];
    int tid  = threadIdx.x;
    int warp = tid >> 5, lane = tid & 31;
    int bid  = blockIdx.x;

    // ---- prologue: all independent loads issued first ----
    float4 x0, x1, x2, x3;
    if (tid < 128) {
        const float4* xr = reinterpret_cast<const float4*>(
            x + (size_t)(bid * 128 + tid) * D_IN);
        x0 = xr[0]; x1 = xr[1]; x2 = xr[2]; x3 = xr[3];
    }
    if (tid >= 128 && tid < 144) {      // warp 4: wa2 = W @ a2
        int r = tid - 128;
        float s = 0.f;
        #pragma unroll
        for (int j = 0; j < DH; ++j) s += W[r * DH + j] * a[DH + j];
        wa2[r] = s;
    }
    float wcol[16];                      // Wk column, in regs across the barrier
    if (tid < 128) {
        int h = tid >> 4, d = tid & 15;
        const float* Wh = Wk + h * (D_IN * D_IN);
        #pragma unroll
        for (int k = 0; k < 16; ++k) wcol[k] = Wh[k * 16 + d];
    }
    __syncthreads();

    // ---- stage A1: per-row products into smem (transposed reduce next) ----
    if (tid < 128) {
        float xv[16] = { x0.x, x0.y, x0.z, x0.w,  x1.x, x1.y, x1.z, x1.w,
                         x2.x, x2.y, x2.z, x2.w,  x3.x, x3.y, x3.z, x3.w };
        // g = <xv, wa2> via explicit tree (shallow dependency chain)
        float t0 = xv[0]*wa2[0]   + xv[1]*wa2[1];
        float t1 = xv[2]*wa2[2]   + xv[3]*wa2[3];
        float t2 = xv[4]*wa2[4]   + xv[5]*wa2[5];
        float t3 = xv[6]*wa2[6]   + xv[7]*wa2[7];
        float t4 = xv[8]*wa2[8]   + xv[9]*wa2[9];
        float t5 = xv[10]*wa2[10] + xv[11]*wa2[11];
        float t6 = xv[12]*wa2[12] + xv[13]*wa2[13];
        float t7 = xv[14]*wa2[14] + xv[15]*wa2[15];
        float g = ((t0+t1)+(t2+t3)) + ((t4+t5)+(t6+t7));
        float e = expf(g);               // |g| <~ 3: safe without max-shift

        float* row = sA + tid * SA_STRIDE;
        #pragma unroll
        for (int k = 0; k < 16; ++k) row[k] = e * xv[k];
        row[16] = e;
    }
    __syncthreads();

    // ---- stage A2: warp w (<17) reduces column w over 128 rows ----
    if (warp < 17) {
        float v = sA[(lane      ) * SA_STRIDE + warp]
                + sA[(lane + 32 ) * SA_STRIDE + warp]
                + sA[(lane + 64 ) * SA_STRIDE + warp]
                + sA[(lane + 96 ) * SA_STRIDE + warp];
        #pragma unroll
        for (int off = 16; off > 0; off >>= 1)
            v += __shfl_down_sync(0xffffffffu, v, off);
        if (lane == 0) g_part[warp * NB + bid] = v;
    }
    __syncthreads();   // partial stores happen-before tid0's release-arrive

    // ---- ticket barrier: no reset, monotonic counter (2^32 % NB == 0) ----
    if (tid == 0) {
        unsigned int old = atom_add_release_gpu(&g_arrive);
        unsigned int target = (old / NB + 1u) * NB;   // end of this round
        while (ld_acquire_gpu(&g_arrive) < target) { }
    }
    __syncthreads();

    // ---- stage B1: warp w (<17) reduces global column w: 64 floats ----
    if (warp < 17) {
        const float* col = g_part + warp * NB;
        float v = col[lane] + col[lane + 32];
        #pragma unroll
        for (int off = 16; off > 0; off >>= 1)
            v += __shfl_down_sync(0xffffffffu, v, off);
        if (lane == 0) red[warp] = v;
    }
    __syncthreads();

    // ---- stage B2: out_row[h*16+d] = (nvec @ Wk[h]) / Z ----
    if (tid < 128) {
        float invZ = 1.0f / red[16];
        float s = 0.f;
        #pragma unroll
        for (int k = 0; k < 16; ++k) s += red[k] * wcol[k];
        orow[tid] = s * invZ;
    }
    __syncthreads();

    // ---- stage B3: broadcast 128 rows = 4096 float4; 512 thr x 8 stores ----
    if (tid < 512) {
        int c4 = tid & 31;               // float4 column 0..31
        int r0 = tid >> 5;               // 0..15
        float4 val = make_float4(orow[c4 * 4 + 0], orow[c4 * 4 + 1],
                                 orow[c4 * 4 + 2], orow[c4 * 4 + 3]);
        float4* o4 = reinterpret_cast<float4*>(out);
        size_t base = (size_t)(bid * 128) * 32;
        #pragma unroll
        for (int i = 0; i < 8; ++i)
            o4[base + (size_t)(r0 + i * 16) * 32 + c4] = val;
    }
    // no tail: kernel ends at last store
}

extern "C" void kernel_launch(void* const* d_in, const int* in_sizes, int n_in,
                              void* d_out, int out_size) {
    const float* x  = (const float*)d_in[0];  // (8192,16)
    const float* W  = (const float*)d_in[1];  // (16,18)
    const float* a  = (const float*)d_in[2];  // (36,1)
    const float* Wk = (const float*)d_in[3];  // (8,16,16)
    float* out = (float*)d_out;               // (8192,128)

    fused_kernel<<<NB, NT>>>(x, W, a, Wk, out);
}